// round 17
// baseline (speedup 1.0000x reference)
#include <cuda_runtime.h>
#include <cuda_bf16.h>
#include <math.h>
#include <stdint.h>

// ---------------- problem constants ----------------
#define D_MODEL 1024
#define NHEAD   16
#define DHEAD   64
#define FF_DIM  4096
#define NSEQ    256
#define NB      4
#define NTOK    50257
#define NEXP    2000
#define NKTOP   20
#define NROWS   (NB*NSEQ)      // 1024
#define QKV_LD  3072
#define NBLK_V  197            // ceil(50257/256)
#define NBH     (NB*NHEAD)     // 64

// fp8 per-tensor scales
#define SX   16.0f
#define SW   512.0f
#define SA   64.0f
#define SF   32.0f
#define SQK  64.0f
#define SP   128.0f

#define LSE_DSM 61440          // As 20480 + Bs 40960 bytes

// ---------------- scratch ----------------
__device__ float g_x    [NROWS*D_MODEL];
__device__ float g_qkv  [NROWS*QKV_LD];
__device__ float g_tmp  [NROWS*D_MODEL];
__device__ float g_sm_attn[NB*D_MODEL];
__device__ float g_sm_x   [NB*D_MODEL];
__device__ float g_sm_tmp [NB*D_MODEL];
__device__ float g_sm_ctx [NB*D_MODEL];
__device__ float g_sm_ffh [NB*FF_DIM];
__device__ float g_psum[NROWS*NBLK_V];
__device__ float g_lse [NROWS];
__device__ float g_lab [NB*(NSEQ-1)];
__device__ float g_stats[32];

// fp8 mirrors
__device__ __align__(256) uint8_t q_Wqkv[2*QKV_LD*D_MODEL];
__device__ __align__(256) uint8_t q_Wo  [2*D_MODEL*D_MODEL];
__device__ __align__(256) uint8_t q_W1  [2*FF_DIM*D_MODEL];
__device__ __align__(256) uint8_t q_W2  [2*D_MODEL*FF_DIM];
__device__ __align__(256) uint8_t q_dec [NTOK*D_MODEL];
__device__ __align__(256) uint8_t q_x   [NROWS*D_MODEL];
__device__ __align__(256) uint8_t q_attn[NROWS*D_MODEL];
__device__ __align__(256) uint8_t q_ffh [NROWS*FF_DIM];
__device__ __align__(256) uint8_t q_qkv [NROWS*QKV_LD];
__device__ __align__(256) uint8_t q_vt  [NBH*DHEAD*NSEQ];

// ---------------- fp8 pack + fast fma-pipe exp ----------------
__device__ __forceinline__ uint16_t pack_e4m3(float lo, float hi)
{
    uint16_t r;
    asm("cvt.rn.satfinite.e4m3x2.f32 %0, %1, %2;" : "=h"(r) : "f"(hi), "f"(lo));
    return r;
}

__device__ __forceinline__ float fast_exp(float x)
{
    float t = x * 1.4426950408889634f;
    float fi = floorf(t);
    float f = t - fi;
    float p = 1.5403530e-4f;
    p = fmaf(p, f, 1.3333558e-3f);
    p = fmaf(p, f, 9.6180489e-3f);
    p = fmaf(p, f, 5.5504109e-2f);
    p = fmaf(p, f, 2.4022651e-1f);
    p = fmaf(p, f, 6.9314718e-1f);
    p = fmaf(p, f, 1.0f);
    return __int_as_float(__float_as_int(p) + (((int)fi) << 23));
}

__global__ void q8_kernel(const float* __restrict__ src, uint8_t* __restrict__ dst,
                          int n4, float scale)
{
    int i = (blockIdx.x*blockDim.x + threadIdx.x) * 2;
    #pragma unroll
    for (int t = 0; t < 2; t++) {
        int j = i + t;
        if (j < n4) {
            float4 v = ((const float4*)src)[j];
            uint32_t lo = pack_e4m3(v.x*scale, v.y*scale);
            uint32_t hi = pack_e4m3(v.z*scale, v.w*scale);
            ((uint32_t*)dst)[j] = lo | (hi << 16);
        }
    }
}

// ---------------- embedding gather ----------------
__global__ void embed_kernel(const int* __restrict__ inputs, const float* __restrict__ emb)
{
    int r = blockIdx.x;
    int tok = inputs[r];
    const float4* src = (const float4*)(emb + (size_t)tok * D_MODEL);
    float4* dst = (float4*)(g_x + (size_t)r * D_MODEL);
    dst[threadIdx.x] = src[threadIdx.x];
}

// ================= cp.async / ldmatrix helpers =================
__device__ __forceinline__ void cp_async16(void* smem, const void* gmem)
{
    uint32_t s = (uint32_t)__cvta_generic_to_shared(smem);
    asm volatile("cp.async.ca.shared.global [%0], [%1], 16;\n" :: "r"(s), "l"(gmem));
}
__device__ __forceinline__ void cp_commit()
{
    asm volatile("cp.async.commit_group;\n" ::: "memory");
}
template<int N> __device__ __forceinline__ void cp_wait()
{
    asm volatile("cp.async.wait_group %0;\n" :: "n"(N) : "memory");
}
__device__ __forceinline__ void ldsm_x4(uint32_t& r0, uint32_t& r1, uint32_t& r2, uint32_t& r3,
                                        const void* smem)
{
    uint32_t a = (uint32_t)__cvta_generic_to_shared(smem);
    asm volatile("ldmatrix.sync.aligned.m8n8.x4.shared.b16 {%0,%1,%2,%3}, [%4];\n"
                 : "=r"(r0), "=r"(r1), "=r"(r2), "=r"(r3) : "r"(a));
}
__device__ __forceinline__ void ldsm_x2(uint32_t& r0, uint32_t& r1, const void* smem)
{
    uint32_t a = (uint32_t)__cvta_generic_to_shared(smem);
    asm volatile("ldmatrix.sync.aligned.m8n8.x2.shared.b16 {%0,%1}, [%2];\n"
                 : "=r"(r0), "=r"(r1) : "r"(a));
}
__device__ __forceinline__ void mma_e4m3(float* a4, uint32_t a0, uint32_t a1, uint32_t a2, uint32_t a3,
                                         uint32_t b0, uint32_t b1)
{
    asm volatile(
        "mma.sync.aligned.m16n8k32.row.col.f32.e4m3.e4m3.f32 "
        "{%0,%1,%2,%3}, {%4,%5,%6,%7}, {%8,%9}, {%0,%1,%2,%3};\n"
        : "+f"(a4[0]), "+f"(a4[1]), "+f"(a4[2]), "+f"(a4[3])
        : "r"(a0), "r"(a1), "r"(a2), "r"(a3), "r"(b0), "r"(b1));
}
__device__ __forceinline__ void mma_tf32(float* a4, uint32_t a0, uint32_t a1, uint32_t a2, uint32_t a3,
                                         uint32_t b0, uint32_t b1)
{
    asm volatile(
        "mma.sync.aligned.m16n8k8.row.col.f32.tf32.tf32.f32 "
        "{%0,%1,%2,%3}, {%4,%5,%6,%7}, {%8,%9}, {%0,%1,%2,%3};\n"
        : "+f"(a4[0]), "+f"(a4[1]), "+f"(a4[2]), "+f"(a4[3])
        : "r"(a0), "r"(a1), "r"(a2), "r"(a3), "r"(b0), "r"(b1));
}

// ================= tf32 GEMM 64x64 (loc KV path) =================
__global__ __launch_bounds__(256) void gemm_tc64_kernel(
    const float* __restrict__ A, const float* __restrict__ W,
    const float* __restrict__ bias, float* __restrict__ C,
    int K, int ldC)
{
    __shared__ uint32_t As[2][64][20];
    __shared__ uint32_t Bs[2][64][20];
    float acc[2][2][4];
    #pragma unroll
    for (int a = 0; a < 2; a++)
        #pragma unroll
        for (int b = 0; b < 2; b++)
            #pragma unroll
            for (int c = 0; c < 4; c++) acc[a][b][c] = 0.f;

    int m0 = blockIdx.y * 64, n0 = blockIdx.x * 64;
    int tid  = threadIdx.x;
    int lane = tid & 31, wid = tid >> 5;
    int wm = wid >> 2, wn = wid & 3;
    int g = lane >> 2, tig = lane & 3;

    int r0c = tid >> 2, c0c = (tid & 3) << 2;
    const float* pa0 = A + (size_t)(m0 + r0c)*K + c0c;
    const float* pb0 = W + (size_t)(n0 + r0c)*K + c0c;

    int niter = K >> 4;
    cp_async16(&As[0][r0c][c0c], pa0);
    cp_async16(&Bs[0][r0c][c0c], pb0);
    cp_commit();

    for (int it = 0; it < niter; it++) {
        int st = it & 1;
        if (it + 1 < niter) {
            int off = (it + 1) << 4;
            int sn = st ^ 1;
            cp_async16(&As[sn][r0c][c0c], pa0 + off);
            cp_async16(&Bs[sn][r0c][c0c], pb0 + off);
            cp_commit();
            cp_wait<1>();
        } else {
            cp_wait<0>();
        }
        __syncthreads();
        #pragma unroll
        for (int ks = 0; ks < 16; ks += 8) {
            uint32_t af[2][4], bf[2][2];
            #pragma unroll
            for (int mt = 0; mt < 2; mt++) {
                int r0 = wm*32 + mt*16;
                af[mt][0] = As[st][r0+g  ][ks+tig  ];
                af[mt][1] = As[st][r0+g+8][ks+tig  ];
                af[mt][2] = As[st][r0+g  ][ks+tig+4];
                af[mt][3] = As[st][r0+g+8][ks+tig+4];
            }
            #pragma unroll
            for (int nt = 0; nt < 2; nt++) {
                int c0 = wn*16 + nt*8;
                bf[nt][0] = Bs[st][c0+g][ks+tig  ];
                bf[nt][1] = Bs[st][c0+g][ks+tig+4];
            }
            #pragma unroll
            for (int mt = 0; mt < 2; mt++)
                #pragma unroll
                for (int nt = 0; nt < 2; nt++)
                    mma_tf32(acc[mt][nt], af[mt][0], af[mt][1], af[mt][2], af[mt][3],
                             bf[nt][0], bf[nt][1]);
        }
        __syncthreads();
    }

    int rowb = m0 + wm*32, colb = n0 + wn*16;
    #pragma unroll
    for (int nt = 0; nt < 2; nt++) {
        int c = colb + nt*8 + 2*tig;
        float b0 = bias[c], b1 = bias[c+1];
        #pragma unroll
        for (int mt = 0; mt < 2; mt++) {
            int r = rowb + mt*16 + g;
            *(float2*)(C + (size_t)r*ldC + c)     = make_float2(acc[mt][nt][0]+b0, acc[mt][nt][1]+b1);
            *(float2*)(C + (size_t)(r+8)*ldC + c) = make_float2(acc[mt][nt][2]+b0, acc[mt][nt][3]+b1);
        }
    }
}

// ================= fp8 decoder lse GEMM: 128x256 tile, warp tile 64x64 =========
__global__ __launch_bounds__(256) void gemm_lse_fp8_kernel(
    const uint8_t* __restrict__ A, const uint8_t* __restrict__ W, int K, float inv)
{
    extern __shared__ uint32_t dsm[];
    uint32_t* As = dsm;                  // [2][128][20]
    uint32_t* Bs = dsm + 2*128*20;       // [2][256][20]

    float acc[4][8][4];
    #pragma unroll
    for (int a = 0; a < 4; a++)
        #pragma unroll
        for (int b = 0; b < 8; b++)
            #pragma unroll
            for (int c = 0; c < 4; c++) acc[a][b][c] = 0.f;

    int m0 = blockIdx.x * 128, n0 = blockIdx.y * 256;
    int nblk = blockIdx.y;

    int tid  = threadIdx.x;
    int lane = tid & 31, wid = tid >> 5;
    int wm = wid >> 2, wn = wid & 3;    // 2 x 4 warps; warp tile 64 x 64
    int g = lane >> 2, tig = lane & 3;

    int a_row = (lane & 7) + ((lane >> 3) & 1) * 8;
    int a_wrd = (lane >> 4) * 4;
    int b_row = lane & 7;
    int b_wrd = ((lane >> 3) & 1) * 4;

    int r0c = tid >> 2;                  // 0..63
    int cw = (tid & 3) * 4;
    int ce = (tid & 3) * 16;
    // A rows: r0c, r0c+64 ; B rows: r0c, +64, +128, +192 (clamped)
    const uint8_t* pa0 = A + (size_t)(m0 + r0c)*K + ce;
    const uint8_t* pa1 = A + (size_t)(m0 + r0c + 64)*K + ce;
    const uint8_t* pb[4];
    #pragma unroll
    for (int i = 0; i < 4; i++) {
        int nr = n0 + r0c + i*64;
        nr = (nr < NTOK) ? nr : (NTOK - 1);
        pb[i] = W + (size_t)nr*K + ce;
    }

    int niter = K >> 6;
    cp_async16(&As[(0*128 + r0c)*20 + cw], pa0);
    cp_async16(&As[(0*128 + r0c + 64)*20 + cw], pa1);
    #pragma unroll
    for (int i = 0; i < 4; i++)
        cp_async16(&Bs[(0*256 + r0c + i*64)*20 + cw], pb[i]);
    cp_commit();

    for (int it = 0; it < niter; it++) {
        int st = it & 1;
        if (it + 1 < niter) {
            int off = (it + 1) << 6;
            int sn = st ^ 1;
            cp_async16(&As[(sn*128 + r0c)*20 + cw], pa0 + off);
            cp_async16(&As[(sn*128 + r0c + 64)*20 + cw], pa1 + off);
            #pragma unroll
            for (int i = 0; i < 4; i++)
                cp_async16(&Bs[(sn*256 + r0c + i*64)*20 + cw], pb[i] + off);
            cp_commit();
            cp_wait<1>();
        } else {
            cp_wait<0>();
        }
        __syncthreads();
        #pragma unroll
        for (int ks = 0; ks < 2; ks++) {
            int kb = ks*8;
            uint32_t af[4][4], bf[8][2];
            #pragma unroll
            for (int mt = 0; mt < 4; mt++) {
                int r0 = wm*64 + mt*16;
                ldsm_x4(af[mt][0], af[mt][1], af[mt][2], af[mt][3],
                        &As[(st*128 + r0 + a_row)*20 + kb + a_wrd]);
            }
            #pragma unroll
            for (int nt = 0; nt < 8; nt++) {
                int c0 = wn*64 + nt*8;
                ldsm_x2(bf[nt][0], bf[nt][1],
                        &Bs[(st*256 + c0 + b_row)*20 + kb + b_wrd]);
            }
            #pragma unroll
            for (int mt = 0; mt < 4; mt++)
                #pragma unroll
                for (int nt = 0; nt < 8; nt++)
                    mma_e4m3(acc[mt][nt], af[mt][0], af[mt][1], af[mt][2], af[mt][3],
                             bf[nt][0], bf[nt][1]);
        }
        __syncthreads();
    }

    // epilogue: per-row sum of exp (no-max; logits bounded), fma-pipe exp
    float* red_s = (float*)dsm;          // [4][128] floats (reuses As region)
    int colb = n0 + wn*64;
    #pragma unroll
    for (int mt = 0; mt < 4; mt++) {
        #pragma unroll
        for (int hh = 0; hh < 2; hh++) {
            float s = 0.f;
            #pragma unroll
            for (int nt = 0; nt < 8; nt++) {
                int c = colb + nt*8 + 2*tig;
                if (c     < NTOK) s += fast_exp(acc[mt][nt][hh*2+0]*inv);
                if (c + 1 < NTOK) s += fast_exp(acc[mt][nt][hh*2+1]*inv);
            }
            s += __shfl_xor_sync(0xffffffffu, s, 1);
            s += __shfl_xor_sync(0xffffffffu, s, 2);
            if (tig == 0) {
                int lr = wm*64 + mt*16 + hh*8 + g;
                red_s[wn*128 + lr] = s;
            }
        }
    }
    __syncthreads();
    if (tid < 128) {
        float s = red_s[0*128 + tid] + red_s[1*128 + tid]
                + red_s[2*128 + tid] + red_s[3*128 + tid];
        int row = m0 + tid;
        g_psum[(size_t)row*NBLK_V + nblk] = s;
    }
}

// ================= fp8 GEMM 64x128 (QKV + FF1): warp tile 32x32 =================
__global__ __launch_bounds__(256) void gemm_fp8_64x128_kernel(
    const uint8_t* __restrict__ A, const uint8_t* __restrict__ W,
    const float* __restrict__ bias, uint8_t* __restrict__ Cout,
    int K, int ldC, float inv, float outscale, int relu)
{
    __shared__ uint32_t As[2][64][20];
    __shared__ uint32_t Bs[2][128][20];

    float acc[2][4][4];
    #pragma unroll
    for (int a = 0; a < 2; a++)
        #pragma unroll
        for (int b = 0; b < 4; b++)
            #pragma unroll
            for (int c = 0; c < 4; c++) acc[a][b][c] = 0.f;

    int m0 = blockIdx.y * 64, n0 = blockIdx.x * 128;

    int tid  = threadIdx.x;
    int lane = tid & 31, wid = tid >> 5;
    int wm = wid >> 2, wn = wid & 3;
    int g = lane >> 2, tig = lane & 3;

    int a_row = (lane & 7) + ((lane >> 3) & 1) * 8;
    int a_wrd = (lane >> 4) * 4;
    int b_row = lane & 7;
    int b_wrd = ((lane >> 3) & 1) * 4;

    int r0c = tid >> 2;
    int cw = (tid & 3) * 4;
    int ce = (tid & 3) * 16;
    const uint8_t* pa0 = A + (size_t)(m0 + r0c)*K + ce;
    const uint8_t* pb0 = W + (size_t)(n0 + r0c)*K + ce;
    const uint8_t* pb1 = W + (size_t)(n0 + r0c + 64)*K + ce;

    int niter = K >> 6;
    cp_async16(&As[0][r0c][cw], pa0);
    cp_async16(&Bs[0][r0c][cw], pb0);
    cp_async16(&Bs[0][r0c + 64][cw], pb1);
    cp_commit();

    for (int it = 0; it < niter; it++) {
        int st = it & 1;
        if (it + 1 < niter) {
            int off = (it + 1) << 6;
            int sn = st ^ 1;
            cp_async16(&As[sn][r0c][cw], pa0 + off);
            cp_async16(&Bs[sn][r0c][cw], pb0 + off);
            cp_async16(&Bs[sn][r0c + 64][cw], pb1 + off);
            cp_commit();
            cp_wait<1>();
        } else {
            cp_wait<0>();
        }
        __syncthreads();
        #pragma unroll
        for (int ks = 0; ks < 2; ks++) {
            int kb = ks*8;
            uint32_t af[2][4], bf[4][2];
            #pragma unroll
            for (int mt = 0; mt < 2; mt++) {
                int r0 = wm*32 + mt*16;
                ldsm_x4(af[mt][0], af[mt][1], af[mt][2], af[mt][3],
                        &As[st][r0 + a_row][kb + a_wrd]);
            }
            #pragma unroll
            for (int nt = 0; nt < 4; nt++) {
                int c0 = wn*32 + nt*8;
                ldsm_x2(bf[nt][0], bf[nt][1],
                        &Bs[st][c0 + b_row][kb + b_wrd]);
            }
            #pragma unroll
            for (int mt = 0; mt < 2; mt++)
                #pragma unroll
                for (int nt = 0; nt < 4; nt++)
                    mma_e4m3(acc[mt][nt], af[mt][0], af[mt][1], af[mt][2], af[mt][3],
                             bf[nt][0], bf[nt][1]);
        }
        __syncthreads();
    }

    #pragma unroll
    for (int a = 0; a < 2; a++)
        #pragma unroll
        for (int b = 0; b < 4; b++)
            #pragma unroll
            for (int c = 0; c < 4; c++) acc[a][b][c] *= inv;

    int rowb = m0 + wm*32, colb = n0 + wn*32;
    #pragma unroll
    for (int nt = 0; nt < 4; nt++) {
        int c = colb + nt*8 + 2*tig;
        float b0 = bias[c], b1 = bias[c+1];
        #pragma unroll
        for (int mt = 0; mt < 2; mt++) {
            int r = rowb + mt*16 + g;
            float v0 = acc[mt][nt][0]+b0, v1 = acc[mt][nt][1]+b1;
            float v2 = acc[mt][nt][2]+b0, v3 = acc[mt][nt][3]+b1;
            if (relu) {
                v0 = fmaxf(v0, 0.f); v1 = fmaxf(v1, 0.f);
                v2 = fmaxf(v2, 0.f); v3 = fmaxf(v3, 0.f);
            }
            *(uint16_t*)(Cout + (size_t)r*ldC + c)     = pack_e4m3(v0*outscale, v1*outscale);
            *(uint16_t*)(Cout + (size_t)(r+8)*ldC + c) = pack_e4m3(v2*outscale, v3*outscale);
        }
    }
}

// ================= fp8 GEMM 64x64 (Wo / FF2) =================
template<int OUT8>
__global__ __launch_bounds__(256) void gemm_fp8_64_kernel(
    const uint8_t* __restrict__ A, const uint8_t* __restrict__ W,
    const float* __restrict__ bias, void* __restrict__ Cout,
    int K, int ldC, float inv, float outscale, int relu)
{
    __shared__ uint32_t As[2][64][20];
    __shared__ uint32_t Bs[2][64][20];

    float acc[2][2][4];
    #pragma unroll
    for (int a = 0; a < 2; a++)
        #pragma unroll
        for (int b = 0; b < 2; b++)
            #pragma unroll
            for (int c = 0; c < 4; c++) acc[a][b][c] = 0.f;

    int m0 = blockIdx.y * 64, n0 = blockIdx.x * 64;

    int tid  = threadIdx.x;
    int lane = tid & 31, wid = tid >> 5;
    int wm = wid >> 2, wn = wid & 3;
    int g = lane >> 2, tig = lane & 3;

    int a_row = (lane & 7) + ((lane >> 3) & 1) * 8;
    int a_wrd = (lane >> 4) * 4;
    int b_row = lane & 7;
    int b_wrd = ((lane >> 3) & 1) * 4;

    int r0c = tid >> 2;
    int cw = (tid & 3) * 4;
    int ce = (tid & 3) * 16;
    const uint8_t* pa0 = A + (size_t)(m0 + r0c)*K + ce;
    const uint8_t* pb0 = W + (size_t)(n0 + r0c)*K + ce;

    int niter = K >> 6;
    cp_async16(&As[0][r0c][cw], pa0);
    cp_async16(&Bs[0][r0c][cw], pb0);
    cp_commit();

    for (int it = 0; it < niter; it++) {
        int st = it & 1;
        if (it + 1 < niter) {
            int off = (it + 1) << 6;
            int sn = st ^ 1;
            cp_async16(&As[sn][r0c][cw], pa0 + off);
            cp_async16(&Bs[sn][r0c][cw], pb0 + off);
            cp_commit();
            cp_wait<1>();
        } else {
            cp_wait<0>();
        }
        __syncthreads();
        #pragma unroll
        for (int ks = 0; ks < 2; ks++) {
            int kb = ks*8;
            uint32_t af[2][4], bf[2][2];
            #pragma unroll
            for (int mt = 0; mt < 2; mt++) {
                int r0 = wm*32 + mt*16;
                ldsm_x4(af[mt][0], af[mt][1], af[mt][2], af[mt][3],
                        &As[st][r0 + a_row][kb + a_wrd]);
            }
            #pragma unroll
            for (int nt = 0; nt < 2; nt++) {
                int c0 = wn*16 + nt*8;
                ldsm_x2(bf[nt][0], bf[nt][1],
                        &Bs[st][c0 + b_row][kb + b_wrd]);
            }
            #pragma unroll
            for (int mt = 0; mt < 2; mt++)
                #pragma unroll
                for (int nt = 0; nt < 2; nt++)
                    mma_e4m3(acc[mt][nt], af[mt][0], af[mt][1], af[mt][2], af[mt][3],
                             bf[nt][0], bf[nt][1]);
        }
        __syncthreads();
    }

    #pragma unroll
    for (int a = 0; a < 2; a++)
        #pragma unroll
        for (int b = 0; b < 2; b++)
            #pragma unroll
            for (int c = 0; c < 4; c++) acc[a][b][c] *= inv;

    int rowb = m0 + wm*32, colb = n0 + wn*16;
    if (OUT8 == 0) {
        float* C = (float*)Cout;
        #pragma unroll
        for (int nt = 0; nt < 2; nt++) {
            int c = colb + nt*8 + 2*tig;
            float b0 = bias[c], b1 = bias[c+1];
            #pragma unroll
            for (int mt = 0; mt < 2; mt++) {
                int r = rowb + mt*16 + g;
                *(float2*)(C + (size_t)r*ldC + c)     = make_float2(acc[mt][nt][0]+b0, acc[mt][nt][1]+b1);
                *(float2*)(C + (size_t)(r+8)*ldC + c) = make_float2(acc[mt][nt][2]+b0, acc[mt][nt][3]+b1);
            }
        }
    } else {
        uint8_t* C = (uint8_t*)Cout;
        #pragma unroll
        for (int nt = 0; nt < 2; nt++) {
            int c = colb + nt*8 + 2*tig;
            float b0 = bias ? bias[c] : 0.f;
            float b1 = bias ? bias[c+1] : 0.f;
            #pragma unroll
            for (int mt = 0; mt < 2; mt++) {
                int r = rowb + mt*16 + g;
                float v0 = acc[mt][nt][0]+b0, v1 = acc[mt][nt][1]+b1;
                float v2 = acc[mt][nt][2]+b0, v3 = acc[mt][nt][3]+b1;
                if (relu) {
                    v0 = fmaxf(v0, 0.f); v1 = fmaxf(v1, 0.f);
                    v2 = fmaxf(v2, 0.f); v3 = fmaxf(v3, 0.f);
                }
                *(uint16_t*)(C + (size_t)r*ldC + c)     = pack_e4m3(v0*outscale, v1*outscale);
                *(uint16_t*)(C + (size_t)(r+8)*ldC + c) = pack_e4m3(v2*outscale, v3*outscale);
            }
        }
    }
}

// ================= V transpose (fp8): [s,d] -> VT[bh][d][s] ==================
__global__ void vtrans_kernel()
{
    __shared__ uint8_t t[64][65];
    int bh = blockIdx.y, b = bh >> 4, h = bh & 15;
    int s0 = blockIdx.x * 64;
    int tid = threadIdx.x;
    const uint8_t* src = q_qkv + (size_t)(b*NSEQ)*QKV_LD + 2*D_MODEL + h*DHEAD;
    for (int i = tid; i < 4096; i += 256) {
        int s = i >> 6, d = i & 63;
        t[d][s] = src[(size_t)(s0+s)*QKV_LD + d];
    }
    __syncthreads();
    uint8_t* dst = q_vt + (size_t)bh*DHEAD*NSEQ;
    for (int i = tid; i < 4096; i += 256) {
        int d = i >> 6, s = i & 63;
        dst[(size_t)d*NSEQ + s0 + s] = t[d][s];
    }
}

// ========== fused attention: scores + softmax + P·V^T per 64-query tile ======
__global__ __launch_bounds__(256) void fattn_kernel()
{
    __shared__ uint32_t sm[11264];                // 45 KB
    uint32_t* Qs = sm;                            // [64][20]
    uint32_t* Ks = sm + 1280;                     // [256][20]
    uint32_t* VT = sm + 6400;                     // [64][68]
    float*    red = (float*)(sm + 10752);         // [64][8]
    uint32_t* Ps = sm;                            // [64][68] (reuses Q/K region)

    int bh = blockIdx.y, b = bh >> 4, h = bh & 15;
    int m0 = blockIdx.x * 64;
    int tid = threadIdx.x, lane = tid & 31, wid = tid >> 5;
    int wm = wid >> 2, wn = wid & 3;              // warps 2 x 4
    int g = lane >> 2, tig = lane & 3;
    int a_row = (lane & 7) + ((lane >> 3) & 1) * 8;
    int a_wrd = (lane >> 4) * 4;
    int b_row = lane & 7;
    int b_wrd = ((lane >> 3) & 1) * 4;

    const uint8_t* Qb  = q_qkv + (size_t)(b*NSEQ)*QKV_LD + h*DHEAD;
    const uint8_t* Kb  = Qb + D_MODEL;
    const uint8_t* VTb = q_vt + (size_t)bh*DHEAD*NSEQ;

    {
        int r = tid >> 2, cw = (tid & 3) * 4, ce = (tid & 3) * 16;
        cp_async16(&Qs[r*20 + cw], Qb + (size_t)(m0 + r)*QKV_LD + ce);
        #pragma unroll
        for (int i = 0; i < 4; i++) {
            int rr = r + i*64;
            cp_async16(&Ks[rr*20 + cw], Kb + (size_t)rr*QKV_LD + ce);
        }
        #pragma unroll
        for (int i = 0; i < 4; i++) {
            int idx = tid + i*256;
            int vr = idx >> 4, vcw = (idx & 15) * 4;
            cp_async16(&VT[vr*68 + vcw], VTb + (size_t)vr*NSEQ + (idx & 15)*16);
        }
        cp_commit(); cp_wait<0>();
    }
    __syncthreads();

    float acc[2][8][4];
    #pragma unroll
    for (int a = 0; a < 2; a++)
        #pragma unroll
        for (int n = 0; n < 8; n++)
            #pragma unroll
            for (int c = 0; c < 4; c++) acc[a][n][c] = 0.f;

    #pragma unroll
    for (int ks = 0; ks < 2; ks++) {
        int kb = ks*8;
        uint32_t af[2][4], bf[8][2];
        #pragma unroll
        for (int mt = 0; mt < 2; mt++) {
            int r0 = wm*32 + mt*16;
            ldsm_x4(af[mt][0], af[mt][1], af[mt][2], af[mt][3],
                    &Qs[(r0 + a_row)*20 + kb + a_wrd]);
        }
        #pragma unroll
        for (int nt = 0; nt < 8; nt++) {
            int c0 = wn*64 + nt*8;
            ldsm_x2(bf[nt][0], bf[nt][1],
                    &Ks[(c0 + b_row)*20 + kb + b_wrd]);
        }
        #pragma unroll
        for (int mt = 0; mt < 2; mt++)
            #pragma unroll
            for (int nt = 0; nt < 8; nt++)
                mma_e4m3(acc[mt][nt], af[mt][0], af[mt][1], af[mt][2], af[mt][3],
                         bf[nt][0], bf[nt][1]);
    }

    const float sc = 0.125f / (SQK*SQK);
    #pragma unroll
    for (int a = 0; a < 2; a++)
        #pragma unroll
        for (int n = 0; n < 8; n++)
            #pragma unroll
            for (int c = 0; c < 4; c++) acc[a][n][c] *= sc;

    #pragma unroll
    for (int mt = 0; mt < 2; mt++) {
        #pragma unroll
        for (int hh = 0; hh < 2; hh++) {
            float m = -INFINITY;
            #pragma unroll
            for (int nt = 0; nt < 8; nt++)
                m = fmaxf(m, fmaxf(acc[mt][nt][hh*2+0], acc[mt][nt][hh*2+1]));
            m = fmaxf(m, __shfl_xor_sync(0xffffffffu, m, 1));
            m = fmaxf(m, __shfl_xor_sync(0xffffffffu, m, 2));
            if (tig == 0) {
                int row = wm*32 + mt*16 + hh*8 + g;
                red[row*8 + wn] = m;
            }
        }
    }
    __syncthreads();
    float rmax[2][2];
    #pragma unroll
    for (int mt = 0; mt < 2; mt++)
        #pragma unroll
        for (int hh = 0; hh < 2; hh++) {
            int row = wm*32 + mt*16 + hh*8 + g;
            rmax[mt][hh] = fmaxf(fmaxf(red[row*8+0], red[row*8+1]),
                                 fmaxf(red[row*8+2], red[row*8+3]));
        }
    #pragma unroll
    for (int mt = 0; mt < 2; mt++) {
        #pragma unroll
        for (int hh = 0; hh < 2; hh++) {
            float s = 0.f;
            #pragma unroll
            for (int nt = 0; nt < 8; nt++) {
                float e0 = fast_exp(acc[mt][nt][hh*2+0] - rmax[mt][hh]);
                float e1 = fast_exp(acc[mt][nt][hh*2+1] - rmax[mt][hh]);
                acc[mt][nt][hh*2+0] = e0;
                acc[mt][nt][hh*2+1] = e1;
                s += e0 + e1;
            }
            s += __shfl_xor_sync(0xffffffffu, s, 1);
            s += __shfl_xor_sync(0xffffffffu, s, 2);
            if (tig == 0) {
                int row = wm*32 + mt*16 + hh*8 + g;
                red[row*8 + 4 + wn] = s;
            }
        }
    }
    __syncthreads();
    float rs[2][2];
    #pragma unroll
    for (int mt = 0; mt < 2; mt++)
        #pragma unroll
        for (int hh = 0; hh < 2; hh++) {
            int row = wm*32 + mt*16 + hh*8 + g;
            rs[mt][hh] = SP / (red[row*8+4] + red[row*8+5] + red[row*8+6] + red[row*8+7]);
        }
    #pragma unroll
    for (int mt = 0; mt < 2; mt++) {
        #pragma unroll
        for (int nt = 0; nt < 8; nt++) {
            int col = wn*64 + nt*8 + 2*tig;
            #pragma unroll
            for (int hh = 0; hh < 2; hh++) {
                int row = wm*32 + mt*16 + hh*8 + g;
                *(uint16_t*)((uint8_t*)&Ps[row*68] + col) =
                    pack_e4m3(acc[mt][nt][hh*2+0]*rs[mt][hh], acc[mt][nt][hh*2+1]*rs[mt][hh]);
            }
        }
    }
    __syncthreads();

    float accO[2][2][4];
    #pragma unroll
    for (int a = 0; a < 2; a++)
        #pragma unroll
        for (int n = 0; n < 2; n++)
            #pragma unroll
            for (int c = 0; c < 4; c++) accO[a][n][c] = 0.f;

    #pragma unroll
    for (int ks = 0; ks < 8; ks++) {
        int kb = ks*8;
        uint32_t af[2][4], bf[2][2];
        #pragma unroll
        for (int mt = 0; mt < 2; mt++) {
            int r0 = wm*32 + mt*16;
            ldsm_x4(af[mt][0], af[mt][1], af[mt][2], af[mt][3],
                    &Ps[(r0 + a_row)*68 + kb + a_wrd]);
        }
        #pragma unroll
        for (int nt = 0; nt < 2; nt++) {
            int c0 = wn*16 + nt*8;
            ldsm_x2(bf[nt][0], bf[nt][1],
                    &VT[(c0 + b_row)*68 + kb + b_wrd]);
        }
        #pragma unroll
        for (int mt = 0; mt < 2; mt++)
            #pragma unroll
            for (int nt = 0; nt < 2; nt++)
                mma_e4m3(accO[mt][nt], af[mt][0], af[mt][1], af[mt][2], af[mt][3],
                         bf[nt][0], bf[nt][1]);
    }

    const float inv = SA / (SP * SQK);
    #pragma unroll
    for (int nt = 0; nt < 2; nt++) {
        int c = wn*16 + nt*8 + 2*tig;
        #pragma unroll
        for (int mt = 0; mt < 2; mt++) {
            int r = m0 + wm*32 + mt*16 + g;
            uint8_t* d0 = q_attn + (size_t)(b*NSEQ + r)*D_MODEL + h*DHEAD + c;
            uint8_t* d1 = q_attn + (size_t)(b*NSEQ + r + 8)*D_MODEL + h*DHEAD + c;
            *(uint16_t*)d0 = pack_e4m3(accO[mt][nt][0]*inv, accO[mt][nt][1]*inv);
            *(uint16_t*)d1 = pack_e4m3(accO[mt][nt][2]*inv, accO[mt][nt][3]*inv);
        }
    }
}

__global__ void lse_reduce_kernel()
{
    int r = blockIdx.x, tid = threadIdx.x;
    double sum = 0.0;
    for (int i = tid; i < NBLK_V; i += 128)
        sum += (double)g_psum[(size_t)r*NBLK_V + i];
    __shared__ double redd[128];
    redd[tid] = sum; __syncthreads();
    for (int s = 64; s > 0; s >>= 1) { if (tid < s) redd[tid] += redd[tid+s]; __syncthreads(); }
    if (tid == 0) g_lse[r] = (float)log(redd[0]);
}

// ---------------- small-M GEMM (one (n,m) pair per block) ----------------
__global__ void rowdot_kernel(
    const float* __restrict__ A, long strideA,
    const float* __restrict__ W, const float* __restrict__ bias,
    float* __restrict__ C, long strideC,
    int K, float alpha, int relu)
{
    int n = blockIdx.x, m = blockIdx.y;
    int tid = threadIdx.x;   // 128
    const float* w = W + (size_t)n * K;
    const float* a = A + (size_t)m * strideA;
    __shared__ float red[128];
    float s = 0.f;
    for (int k = tid; k < K; k += 128) s += a[k]*w[k];
    red[tid] = s; __syncthreads();
    for (int st = 64; st > 0; st >>= 1) { if (tid < st) red[tid] += red[tid+st]; __syncthreads(); }
    if (tid == 0) {
        float v = alpha*red[0] + (bias ? bias[n] : 0.f);
        if (relu) v = fmaxf(v, 0.f);
        C[(size_t)m*strideC + n] = v;
    }
}

// ---------------- loc attention (single query per (h,b)), fp32 out ----------------
__global__ __launch_bounds__(256) void attn_kernel(
    const float* __restrict__ qkv, float* __restrict__ out, int nq, int sq_base)
{
    int qi = blockIdx.x, h = blockIdx.y, b = blockIdx.z;
    int sq = sq_base + qi;
    int tid = threadIdx.x;
    __shared__ float4 qrow[DHEAD/4];
    __shared__ float sc[NSEQ];
    __shared__ float red[256];
    __shared__ float sden;
    __shared__ float osum[4][DHEAD];
    const float* base = qkv + (size_t)b * NSEQ * QKV_LD;
    if (tid < DHEAD/4)
        qrow[tid] = ((const float4*)(base + (size_t)sq*QKV_LD + h*DHEAD))[tid];
    __syncthreads();
    {
        const float4* krow = (const float4*)(base + (size_t)tid*QKV_LD + D_MODEL + h*DHEAD);
        float d = 0.f;
        #pragma unroll
        for (int t = 0; t < DHEAD/4; t++) {
            float4 k4 = krow[t];
            float4 q4 = qrow[t];
            d += q4.x*k4.x + q4.y*k4.y + q4.z*k4.z + q4.w*k4.w;
        }
        sc[tid] = d * 0.125f;
    }
    __syncthreads();
    red[tid] = sc[tid]; __syncthreads();
    for (int s = 128; s > 0; s >>= 1) { if (tid < s) red[tid] = fmaxf(red[tid], red[tid+s]); __syncthreads(); }
    float mx = red[0]; __syncthreads();
    float e = expf(sc[tid] - mx);
    red[tid] = e; __syncthreads();
    for (int s = 128; s > 0; s >>= 1) { if (tid < s) red[tid] += red[tid+s]; __syncthreads(); }
    if (tid == 0) sden = red[0];
    __syncthreads();
    sc[tid] = e;
    __syncthreads();
    int d = tid & 63, g = tid >> 6;
    const float* vb = base + 2*D_MODEL + h*DHEAD + d;
    float o = 0.f;
    for (int j = g*64; j < (g+1)*64; j++) o += sc[j] * vb[(size_t)j*QKV_LD];
    osum[g][d] = o; __syncthreads();
    if (tid < DHEAD) {
        float r = (osum[0][tid]+osum[1][tid]+osum[2][tid]+osum[3][tid]) / sden;
        out[((size_t)(b*nq + qi))*D_MODEL + h*DHEAD + tid] = r;
    }
}

// ---------------- residual + layernorm (fp32 out + optional fp8 mirror) ----------
__global__ void ln_kernel(
    const float* __restrict__ in1, long s1,
    const float* __restrict__ in2, long s2,
    float* __restrict__ out, long so,
    uint8_t* __restrict__ outq, float qs,
    const float* __restrict__ gam, const float* __restrict__ bet)
{
    int r = blockIdx.x, tid = threadIdx.x;
    __shared__ float xr[D_MODEL];
    __shared__ float red[256];
    const float* p1 = in1 + (size_t)r*s1;
    const float* p2 = in2 + (size_t)r*s2;
    float ls = 0.f;
    for (int d = tid; d < D_MODEL; d += 256) { float v = p1[d]+p2[d]; xr[d] = v; ls += v; }
    red[tid] = ls; __syncthreads();
    for (int s = 128; s > 0; s >>= 1) { if (tid < s) red[tid] += red[tid+s]; __syncthreads(); }
    float mean = red[0] * (1.f/D_MODEL); __syncthreads();
    float lv = 0.f;
    for (int d = tid; d < D_MODEL; d += 256) { float t = xr[d]-mean; lv += t*t; }
    red[tid] = lv; __syncthreads();
    for (int s = 128; s > 0; s >>= 1) { if (tid < s) red[tid] += red[tid+s]; __syncthreads(); }
    float rstd = 1.f / sqrtf(red[0]*(1.f/D_MODEL) + 1e-5f);
    for (int d = tid*2; d < D_MODEL; d += 512) {
        float v0 = (xr[d]  -mean)*rstd*gam[d]   + bet[d];
        float v1 = (xr[d+1]-mean)*rstd*gam[d+1] + bet[d+1];
        *(float2*)(out + (size_t)r*so + d) = make_float2(v0, v1);
        if (outq) *(uint16_t*)(outq + (size_t)r*D_MODEL + d) = pack_e4m3(v0*qs, v1*qs);
    }
}

// ---------------- gating statistics + top-k + softmax + importance ----------------
__global__ void stats_kernel(const float* __restrict__ w, const float* __restrict__ noise)
{
    __shared__ float tot[NEXP];
    __shared__ double redd[256];
    __shared__ float wv[8];
    __shared__ int   wi[8];
    __shared__ float topv[NKTOP];
    __shared__ double smean, sstd;
    int tid = threadIdx.x;
    double ls = 0.0;
    for (int n = tid; n < NEXP; n += 256) {
        float f = 0.25f*(w[n] + w[NEXP+n] + w[2*NEXP+n] + w[3*NEXP+n]);
        tot[n] = f; ls += (double)f;
    }
    redd[tid] = ls; __syncthreads();
    for (int s = 128; s > 0; s >>= 1) { if (tid < s) redd[tid] += redd[tid+s]; __syncthreads(); }
    if (tid == 0) smean = redd[0] / NEXP;
    __syncthreads();
    double mfm = smean;
    ls = 0.0;
    for (int n = tid; n < NEXP; n += 256) { double t = (double)tot[n]-mfm; ls += t*t; }
    redd[tid] = ls; __syncthreads();
    for (int s = 128; s > 0; s >>= 1) { if (tid < s) redd[tid] += redd[tid+s]; __syncthreads(); }
    if (tid == 0) sstd = sqrt(redd[0] / (NEXP-1));
    __syncthreads();
    float stdfm = (float)sstd;
    for (int n = tid; n < NEXP; n += 256) tot[n] = tot[n] + noise[n]*stdfm;
    __syncthreads();
    ls = 0.0;
    for (int n = tid; n < NEXP; n += 256) ls += (double)tot[n];
    redd[tid] = ls; __syncthreads();
    for (int s = 128; s > 0; s >>= 1) { if (tid < s) redd[tid] += redd[tid+s]; __syncthreads(); }
    if (tid == 0) smean = redd[0] / NEXP;
    __syncthreads();
    double mt = smean;
    ls = 0.0;
    for (int n = tid; n < NEXP; n += 256) { double t = (double)tot[n]-mt; ls += t*t; }
    redd[tid] = ls; __syncthreads();
    for (int s = 128; s > 0; s >>= 1) { if (tid < s) redd[tid] += redd[tid+s]; __syncthreads(); }
    if (tid == 0) {
        double st = sqrt(redd[0] / (NEXP-1));
        double ratio = st / mt;
        g_stats[20] = (float)(0.1 * ratio * ratio);
    }
    __syncthreads();
    for (int it = 0; it < NKTOP; it++) {
        float bv = -INFINITY; int bi = 0x7fffffff;
        for (int n = tid; n < NEXP; n += 256) {
            float v = tot[n];
            if (v > bv || (v == bv && n < bi)) { bv = v; bi = n; }
        }
        #pragma unroll
        for (int o = 16; o; o >>= 1) {
            float ov = __shfl_down_sync(0xffffffffu, bv, o);
            int   oi = __shfl_down_sync(0xffffffffu, bi, o);
            if (ov > bv || (ov == bv && oi < bi)) { bv = ov; bi = oi; }
        }
        if ((tid & 31) == 0) { wv[tid >> 5] = bv; wi[tid >> 5] = bi; }
        __syncthreads();
        if (tid == 0) {
            float fbv = wv[0]; int fbi = wi[0];
            #pragma unroll
            for (int ww = 1; ww < 8; ww++)
                if (wv[ww] > fbv || (wv[ww] == fbv && wi[ww] < fbi)) { fbv = wv[ww]; fbi = wi[ww]; }
            topv[it] = fbv; tot[fbi] = -INFINITY;
        }
        __syncthreads();
    }
    if (tid == 0) {
        float m = topv[0];
        float s = 0.f;
        float e[NKTOP];
        for (int k = 0; k < NKTOP; k++) { e[k] = expf(topv[k]-m); s += e[k]; }
        for (int k = 0; k < NKTOP; k++) g_stats[k] = e[k]/s;
    }
}

// ---------------- response mixture (fp32 + fp8 mirror) ----------------
__global__ void mix_kernel(const float* __restrict__ responses)
{
    __shared__ float w[NKTOP];
    if (threadIdx.x < NKTOP) w[threadIdx.x] = g_stats[threadIdx.x];
    __syncthreads();
    int i = blockIdx.x*blockDim.x + threadIdx.x;
    if (i < (NROWS*D_MODEL)/4) {
        float4 s = make_float4(0.f, 0.f, 0.f, 0.f);
        #pragma unroll
        for (int k = 0; k < NKTOP; k++) {
            float4 v = ((const float4*)responses)[(size_t)k*((NROWS*D_MODEL)/4) + i];
            float wk = w[k];
            s.x += wk*v.x; s.y += wk*v.y; s.z += wk*v.z; s.w += wk*v.w;
        }
        ((float4*)g_x)[i] = s;
        uint32_t lo = pack_e4m3(s.x*SX, s.y*SX);
        uint32_t hi = pack_e4m3(s.z*SX, s.w*SX);
        ((uint32_t*)q_x)[i] = lo | (hi << 16);
    }
}

// ---------------- label logit + final loss ----------------
__global__ void lablogit_kernel(const int* __restrict__ inputs, const float* __restrict__ dec_w)
{
    int s = blockIdx.x, b = blockIdx.y, tid = threadIdx.x;
    int lbl = inputs[b*NSEQ + s + 1];
    const float* a = g_x + ((size_t)(b*NSEQ + s))*D_MODEL;
    const float* wp = dec_w + (size_t)lbl*D_MODEL;
    __shared__ float red[128];
    float acc = 0.f;
    for (int k = tid; k < D_MODEL; k += 128) acc += a[k]*wp[k];
    red[tid] = acc; __syncthreads();
    for (int st = 64; st > 0; st >>= 1) { if (tid < st) red[tid] += red[tid+st]; __syncthreads(); }
    if (tid == 0) g_lab[b*(NSEQ-1)+s] = red[0];
}

__global__ void final_kernel(float* __restrict__ out)
{
    __shared__ double red[256];
    int tid = threadIdx.x;
    double s = 0.0;
    for (int i = tid; i < NB*(NSEQ-1); i += 256) {
        int b = i/(NSEQ-1), sp = i%(NSEQ-1);
        s += (double)g_lab[i] - (double)g_lse[b*NSEQ+sp];
    }
    red[tid] = s; __syncthreads();
    for (int st = 128; st > 0; st >>= 1) { if (tid < st) red[tid] += red[tid+st]; __syncthreads(); }
    if (tid == 0) {
        double ce = -red[0] / (double)(NB*(NSEQ-1));
        out[0] = (float)(ce + (double)g_stats[20]);
    }
}

// ---------------- host driver ----------------
extern "C" void kernel_launch(void* const* d_in, const int* in_sizes, int n_in,
                              void* d_out, int out_size)
{
    (void)in_sizes; (void)n_in; (void)out_size;
    const int*   inputs    = (const int*)  d_in[0];
    const float* responses = (const float*)d_in[1];
    const float* noise     = (const float*)d_in[2];
    const float* emb       = (const float*)d_in[3];
    const float* loc_Wqkv  = (const float*)d_in[4];
    const float* loc_bqkv  = (const float*)d_in[5];
    const float* loc_Wo    = (const float*)d_in[6];
    const float* loc_bo    = (const float*)d_in[7];
    const float* loc_ln1g  = (const float*)d_in[8];
    const float* loc_ln1b  = (const float*)d_in[9];
    const float* loc_W1    = (const float*)d_in[10];
    const float* loc_b1    = (const float*)d_in[11];
    const float* loc_W2    = (const float*)d_in[12];
    const float* loc_b2    = (const float*)d_in[13];
    const float* loc_ln2g  = (const float*)d_in[14];
    const float* loc_ln2b  = (const float*)d_in[15];
    const float* enc_Wqkv  = (const float*)d_in[16];
    const float* enc_bqkv  = (const float*)d_in[17];
    const float* enc_Wo    = (const float*)d_in[18];
    const float* enc_bo    = (const float*)d_in[19];
    const float* enc_ln1g  = (const float*)d_in[20];
    const float* enc_ln1b  = (const float*)d_in[21];
    const float* enc_W1    = (const float*)d_in[22];
    const float* enc_b1    = (const float*)d_in[23];
    const float* enc_W2    = (const float*)d_in[24];
    const float* enc_b2    = (const float*)d_in[25];
    const float* enc_ln2g  = (const float*)d_in[26];
    const float* enc_ln2b  = (const float*)d_in[27];
    const float* gate_w    = (const float*)d_in[28];
    const float* gate_b    = (const float*)d_in[29];
    const float* dec_w     = (const float*)d_in[30];
    float* out = (float*)d_out;

    float *p_x, *p_qkv, *p_tmp;
    float *p_sm_attn, *p_sm_x, *p_sm_tmp, *p_sm_ctx, *p_sm_ffh;
    uint8_t *p_qWqkv, *p_qWo, *p_qW1, *p_qW2, *p_qdec, *p_qx, *p_qattn, *p_qffh, *p_qqkv;
    cudaGetSymbolAddress((void**)&p_x, g_x);
    cudaGetSymbolAddress((void**)&p_qkv, g_qkv);
    cudaGetSymbolAddress((void**)&p_tmp, g_tmp);
    cudaGetSymbolAddress((void**)&p_sm_attn, g_sm_attn);
    cudaGetSymbolAddress((void**)&p_sm_x, g_sm_x);
    cudaGetSymbolAddress((void**)&p_sm_tmp, g_sm_tmp);
    cudaGetSymbolAddress((void**)&p_sm_ctx, g_sm_ctx);
    cudaGetSymbolAddress((void**)&p_sm_ffh, g_sm_ffh);
    cudaGetSymbolAddress((void**)&p_qWqkv, q_Wqkv);
    cudaGetSymbolAddress((void**)&p_qWo, q_Wo);
    cudaGetSymbolAddress((void**)&p_qW1, q_W1);
    cudaGetSymbolAddress((void**)&p_qW2, q_W2);
    cudaGetSymbolAddress((void**)&p_qdec, q_dec);
    cudaGetSymbolAddress((void**)&p_qx, q_x);
    cudaGetSymbolAddress((void**)&p_qattn, q_attn);
    cudaGetSymbolAddress((void**)&p_qffh, q_ffh);
    cudaGetSymbolAddress((void**)&p_qqkv, q_qkv);

    cudaFuncSetAttribute(gemm_lse_fp8_kernel,
                         cudaFuncAttributeMaxDynamicSharedMemorySize, LSE_DSM);

    // ---- capture-forked side stream for weight conversions ----
    cudaStream_t s2;
    cudaStreamCreateWithFlags(&s2, cudaStreamNonBlocking);
    cudaEvent_t evFork, evEnc, evDec;
    cudaEventCreateWithFlags(&evFork, cudaEventDisableTiming);
    cudaEventCreateWithFlags(&evEnc,  cudaEventDisableTiming);
    cudaEventCreateWithFlags(&evDec,  cudaEventDisableTiming);

    cudaEventRecord(evFork, 0);
    cudaStreamWaitEvent(s2, evFork, 0);

    q8_kernel<<<(2*QKV_LD*D_MODEL/8 + 255)/256, 256, 0, s2>>>(enc_Wqkv, p_qWqkv, 2*QKV_LD*D_MODEL/4, SW);
    q8_kernel<<<(2*D_MODEL*D_MODEL/8 + 255)/256, 256, 0, s2>>>(enc_Wo, p_qWo, 2*D_MODEL*D_MODEL/4, SW);
    q8_kernel<<<(2*FF_DIM*D_MODEL/8 + 255)/256, 256, 0, s2>>>(enc_W1, p_qW1, 2*FF_DIM*D_MODEL/4, SW);
    q8_kernel<<<(2*D_MODEL*FF_DIM/8 + 255)/256, 256, 0, s2>>>(enc_W2, p_qW2, 2*D_MODEL*FF_DIM/4, SW);
    cudaEventRecord(evEnc, s2);
    q8_kernel<<<(NTOK*D_MODEL/8 + 255)/256, 256, 0, s2>>>(dec_w, p_qdec, NTOK*D_MODEL/4, SW);
    cudaEventRecord(evDec, s2);

    // default stream: embed + loc layer + gating
    embed_kernel<<<NROWS, 256>>>(inputs, emb);
    gemm_tc64_kernel<<<dim3(2048/64, NROWS/64), 256>>>(
        p_x, loc_Wqkv + (size_t)D_MODEL*D_MODEL, loc_bqkv + D_MODEL,
        p_qkv + D_MODEL, D_MODEL, QKV_LD);
    rowdot_kernel<<<dim3(D_MODEL, NB), 128>>>(
        p_x + (size_t)(NSEQ-1)*D_MODEL, (long)NSEQ*D_MODEL,
        loc_Wqkv, loc_bqkv,
        p_qkv + (size_t)(NSEQ-1)*QKV_LD, (long)NSEQ*QKV_LD,
        D_MODEL, 1.f, 0);
    attn_kernel<<<dim3(1, NHEAD, NB), 256>>>(p_qkv, p_sm_attn, 1, NSEQ-1);
    rowdot_kernel<<<dim3(D_MODEL, NB), 128>>>(p_sm_attn, D_MODEL, loc_Wo, loc_bo,
                                              p_sm_tmp, D_MODEL, D_MODEL, 1.f, 0);
    ln_kernel<<<NB, 256>>>(p_x + (size_t)(NSEQ-1)*D_MODEL, (long)NSEQ*D_MODEL,
                           p_sm_tmp, D_MODEL, p_sm_x, D_MODEL, (uint8_t*)0, 0.f,
                           loc_ln1g, loc_ln1b);
    rowdot_kernel<<<dim3(FF_DIM, NB), 128>>>(p_sm_x, D_MODEL, loc_W1, loc_b1,
                                             p_sm_ffh, FF_DIM, D_MODEL, 1.f, 1);
    rowdot_kernel<<<dim3(D_MODEL, NB), 128>>>(p_sm_ffh, FF_DIM, loc_W2, loc_b2,
                                              p_sm_tmp, D_MODEL, FF_DIM, 1.f, 0);
    ln_kernel<<<NB, 256>>>(p_sm_x, D_MODEL, p_sm_tmp, D_MODEL,
                           p_sm_ctx, D_MODEL, (uint8_t*)0, 0.f,
                           loc_ln2g, loc_ln2b);

    rowdot_kernel<<<dim3(NEXP, NB), 128>>>(p_sm_ctx, D_MODEL, gate_w, gate_b,
                                           out + 1, NEXP, D_MODEL, 32.f, 0);
    stats_kernel<<<1, 256>>>(out + 1, noise);
    mix_kernel<<<(NROWS*D_MODEL/4 + 255)/256, 256>>>(responses);

    cudaStreamWaitEvent(0, evEnc, 0);

    // two encoder layers: fp8 GEMMs + fused fp8 attention
    const float invXW = 1.f/(SX*SW);
    const float invAW = 1.f/(SA*SW);
    const float invFW = 1.f/(SF*SW);
    for (int l = 0; l < 2; l++) {
        const uint8_t* Wqkv = p_qWqkv + (size_t)l*QKV_LD*D_MODEL;
        const float*   bqkv = enc_bqkv + (size_t)l*QKV_LD;
        const uint8_t* Wo   = p_qWo   + (size_t)l*D_MODEL*D_MODEL;
        const float*   bo   = enc_bo  + (size_t)l*D_MODEL;
        const float* g1   = enc_ln1g + (size_t)l*D_MODEL;
        const float* b1l  = enc_ln1b + (size_t)l*D_MODEL;
        const uint8_t* W1   = p_qW1   + (size_t)l*FF_DIM*D_MODEL;
        const float*   bb1  = enc_b1  + (size_t)l*FF_DIM;
        const uint8_t* W2   = p_qW2   + (size_t)l*D_MODEL*FF_DIM;
        const float*   bb2  = enc_b2  + (size_t)l*D_MODEL;
        const float* g2   = enc_ln2g + (size_t)l*D_MODEL;
        const float* b2l  = enc_ln2b + (size_t)l*D_MODEL;

        gemm_fp8_64x128_kernel<<<dim3(QKV_LD/128, NROWS/64), 256>>>(
            p_qx, Wqkv, bqkv, p_qqkv, D_MODEL, QKV_LD, invXW, SQK, 0);
        vtrans_kernel<<<dim3(4, NBH), 256>>>();
        fattn_kernel<<<dim3(NSEQ/64, NBH), 256>>>();
        gemm_fp8_64_kernel<0><<<dim3(D_MODEL/64, NROWS/64), 256>>>(
            p_qattn, Wo, bo, p_tmp, D_MODEL, D_MODEL, invAW, 0.f, 0);
        ln_kernel<<<NROWS, 256>>>(p_x, D_MODEL, p_tmp, D_MODEL, p_x, D_MODEL,
                                  p_qx, SX, g1, b1l);
        gemm_fp8_64x128_kernel<<<dim3(FF_DIM/128, NROWS/64), 256>>>(
            p_qx, W1, bb1, p_qffh, D_MODEL, FF_DIM, invXW, SF, 1);
        gemm_fp8_64_kernel<0><<<dim3(D_MODEL/64, NROWS/64), 256>>>(
            p_qffh, W2, bb2, p_tmp, FF_DIM, D_MODEL, invFW, 0.f, 0);
        ln_kernel<<<NROWS, 256>>>(p_x, D_MODEL, p_tmp, D_MODEL, p_x, D_MODEL,
                                  p_qx, SX, g2, b2l);
    }

    cudaStreamWaitEvent(0, evDec, 0);

    // fp8 decoder lse GEMM, 128x256 tiles (m-tiles adjacent for L2 reuse)
    gemm_lse_fp8_kernel<<<dim3(NROWS/128, NBLK_V), 256, LSE_DSM>>>(
        p_qx, p_qdec, D_MODEL, 1.f/(SX*SW));
    lse_reduce_kernel<<<NROWS, 128>>>();
    lablogit_kernel<<<dim3(NSEQ-1, NB), 128>>>(inputs, dec_w);
    final_kernel<<<1, 256>>>(out);

    cudaEventDestroy(evFork);
    cudaEventDestroy(evEnc);
    cudaEventDestroy(evDec);
    cudaStreamDestroy(s2);
}